// round 1
// baseline (speedup 1.0000x reference)
#include <cuda_runtime.h>
#include <math.h>

#define NFULL 50000
#define NPOOL 12500
#define EFULL 600000
#define EPOOL 150000
#define DD    128

// ---------------- device scratch (no allocation allowed) ----------------
__device__ float d_ypool[NPOOL * DD];
__device__ float d_accpool[NPOOL * DD];
__device__ float d_h[NPOOL * DD];
__device__ float d_y[NFULL * DD];
__device__ float d_acc[NFULL * DD];
__device__ float d_xf1[NFULL * DD];
__device__ int   d_degp[NPOOL];
__device__ int   d_degf[NFULL];
__device__ float d_dinvp[NPOOL];
__device__ float d_dinvf[NFULL];
__device__ int   d_mask[NFULL];

// ---------------- utility kernels ----------------
__global__ void zero_f4_kernel(float4* p, int n4) {
    int i = blockIdx.x * blockDim.x + threadIdx.x;
    int stride = gridDim.x * blockDim.x;
    float4 z = make_float4(0.f, 0.f, 0.f, 0.f);
    for (; i < n4; i += stride) p[i] = z;
}

__global__ void zero_i_kernel(int* p, int n) {
    int i = blockIdx.x * blockDim.x + threadIdx.x;
    int stride = gridDim.x * blockDim.x;
    for (; i < n; i += stride) p[i] = 0;
}

__global__ void deg_kernel(const int* __restrict__ dst, int E, int* __restrict__ deg) {
    int i = blockIdx.x * blockDim.x + threadIdx.x;
    int stride = gridDim.x * blockDim.x;
    for (; i < E; i += stride) atomicAdd(&deg[dst[i]], 1);
}

__global__ void dinv_kernel(const int* __restrict__ deg, float* __restrict__ dinv, int n) {
    int i = blockIdx.x * blockDim.x + threadIdx.x;
    int stride = gridDim.x * blockDim.x;
    for (; i < n; i += stride) dinv[i] = rsqrtf((float)(deg[i] + 1));
}

__global__ void mask_kernel(const int* __restrict__ remap, int n, int* __restrict__ mask) {
    int i = blockIdx.x * blockDim.x + threadIdx.x;
    if (i < n) mask[remap[i]] = 1;
}

// ---------------- GEMM: y[node] = acc[node] = dinv[node] * (X[row] @ W) ----------------
// BM=64 rows x BN=128 cols (full D), BK=32. 256 threads, each 8x4 register tile.
template <int REMAP>
__global__ __launch_bounds__(256) void gemm_kernel(
    const float* __restrict__ X, const float* __restrict__ W, int M,
    const float* __restrict__ dinv, const int* __restrict__ remap,
    float* __restrict__ y, float* __restrict__ acc)
{
    __shared__ float As[64][33];
    __shared__ float Bs[32][128];
    int tid = threadIdx.x;
    int tx = tid & 31;   // column group: cols tx*4 .. tx*4+3
    int ty = tid >> 5;   // row group: rows ty*8 .. ty*8+7
    int rowBase = blockIdx.x * 64;

    float accr[8][4];
#pragma unroll
    for (int r = 0; r < 8; r++)
#pragma unroll
        for (int c = 0; c < 4; c++) accr[r][c] = 0.f;

    for (int k0 = 0; k0 < 128; k0 += 32) {
        // load A tile: 64x32 floats = 512 float4, 2 per thread
#pragma unroll
        for (int s = 0; s < 2; s++) {
            int idx = tid * 2 + s;       // 0..511
            int r = idx >> 3;            // 8 float4 per row
            int c4 = idx & 7;
            float4 v = make_float4(0.f, 0.f, 0.f, 0.f);
            int grow = rowBase + r;
            if (grow < M) v = *(const float4*)(X + grow * 128 + k0 + c4 * 4);
            As[r][c4 * 4 + 0] = v.x;
            As[r][c4 * 4 + 1] = v.y;
            As[r][c4 * 4 + 2] = v.z;
            As[r][c4 * 4 + 3] = v.w;
        }
        // load B tile: 32x128 floats = 1024 float4, 4 per thread
#pragma unroll
        for (int s = 0; s < 4; s++) {
            int idx = tid * 4 + s;       // 0..1023
            int r = idx >> 5;            // 32 float4 per row
            int c4 = idx & 31;
            float4 v = *(const float4*)(W + (k0 + r) * 128 + c4 * 4);
            *(float4*)&Bs[r][c4 * 4] = v;
        }
        __syncthreads();
#pragma unroll
        for (int k = 0; k < 32; k++) {
            float a[8];
#pragma unroll
            for (int r = 0; r < 8; r++) a[r] = As[ty * 8 + r][k];
            float4 b = *(float4*)&Bs[k][tx * 4];
#pragma unroll
            for (int r = 0; r < 8; r++) {
                accr[r][0] = fmaf(a[r], b.x, accr[r][0]);
                accr[r][1] = fmaf(a[r], b.y, accr[r][1]);
                accr[r][2] = fmaf(a[r], b.z, accr[r][2]);
                accr[r][3] = fmaf(a[r], b.w, accr[r][3]);
            }
        }
        __syncthreads();
    }

#pragma unroll
    for (int r = 0; r < 8; r++) {
        int row = rowBase + ty * 8 + r;
        if (row < M) {
            int node = REMAP ? remap[row] : row;
            float s = dinv[node];
            float4 v = make_float4(accr[r][0] * s, accr[r][1] * s,
                                   accr[r][2] * s, accr[r][3] * s);
            *(float4*)(y + node * 128 + tx * 4) = v;
            *(float4*)(acc + node * 128 + tx * 4) = v;
        }
    }
}

// ---------------- edge scatter: acc[dst] += y[src] (vector atomic) ----------------
template <bool USE_MASK>
__global__ __launch_bounds__(256) void edge_kernel(
    const int* __restrict__ src, const int* __restrict__ dst, int E,
    const float* __restrict__ y, float* __restrict__ acc,
    const int* __restrict__ mask)
{
    int lane = threadIdx.x & 31;
    int w = (blockIdx.x * blockDim.x + threadIdx.x) >> 5;
    int nw = (gridDim.x * blockDim.x) >> 5;
    for (int e = w; e < E; e += nw) {
        int s = src[e];
        if (USE_MASK) {
            if (mask[s] == 0) continue;
        }
        int d = dst[e];
        float4 v = *(const float4*)(y + s * 128 + lane * 4);
        float* p = acc + d * 128 + lane * 4;
        asm volatile("red.global.add.v4.f32 [%0], {%1, %2, %3, %4};"
                     :: "l"(p), "f"(v.x), "f"(v.y), "f"(v.z), "f"(v.w)
                     : "memory");
    }
}

// ---------------- finalize: out = elu(dinv[row]*acc + b[col]) ----------------
__device__ __forceinline__ float elu1(float x) {
    return x > 0.f ? x : expm1f(x);
}

__global__ __launch_bounds__(256) void finalize_kernel(
    const float* __restrict__ acc, const float* __restrict__ dinv,
    const float* __restrict__ b, float* __restrict__ out, int n)
{
    int i = blockIdx.x * blockDim.x + threadIdx.x;   // over n*32 float4s
    int stride = gridDim.x * blockDim.x;
    int total = n * 32;
    for (; i < total; i += stride) {
        int row = i >> 5;
        int c4 = i & 31;
        float s = dinv[row];
        float4 v = *(const float4*)(acc + row * 128 + c4 * 4);
        float4 bb = *(const float4*)(b + c4 * 4);
        float4 o;
        o.x = elu1(fmaf(s, v.x, bb.x));
        o.y = elu1(fmaf(s, v.y, bb.y));
        o.z = elu1(fmaf(s, v.z, bb.z));
        o.w = elu1(fmaf(s, v.w, bb.w));
        *(float4*)(out + row * 128 + c4 * 4) = o;
    }
}

// ---------------- launch ----------------
extern "C" void kernel_launch(void* const* d_in, const int* in_sizes, int n_in,
                              void* d_out, int out_size)
{
    const int* ei  = (const int*)d_in[1];
    const float* px = (const float*)d_in[2];
    const int* pei = (const int*)d_in[3];
    const int* up  = (const int*)d_in[4];
    const float* W0 = (const float*)d_in[5];
    const float* b0 = (const float*)d_in[6];
    const float* W1 = (const float*)d_in[7];
    const float* b1 = (const float*)d_in[8];
    const float* W2 = (const float*)d_in[9];
    const float* b2 = (const float*)d_in[10];
    float* out = (float*)d_out;

    int nf = in_sizes[0] / DD;
    int ef = in_sizes[1] / 2;
    int np = in_sizes[2] / DD;
    int ep = in_sizes[3] / 2;

    // resolve device scratch addresses
    float *ypool, *accpool, *h, *y, *acc, *xf1, *dinvp, *dinvf;
    int *degp, *degf, *mask;
    cudaGetSymbolAddress((void**)&ypool,  d_ypool);
    cudaGetSymbolAddress((void**)&accpool,d_accpool);
    cudaGetSymbolAddress((void**)&h,      d_h);
    cudaGetSymbolAddress((void**)&y,      d_y);
    cudaGetSymbolAddress((void**)&acc,    d_acc);
    cudaGetSymbolAddress((void**)&xf1,    d_xf1);
    cudaGetSymbolAddress((void**)&degp,   d_degp);
    cudaGetSymbolAddress((void**)&degf,   d_degf);
    cudaGetSymbolAddress((void**)&dinvp,  d_dinvp);
    cudaGetSymbolAddress((void**)&dinvf,  d_dinvf);
    cudaGetSymbolAddress((void**)&mask,   d_mask);

    const int T = 256;
    auto cdiv = [](int a, int b) { return (a + b - 1) / b; };

    // 1. zero scratch that needs it
    zero_f4_kernel<<<cdiv(nf * 32, T), T>>>((float4*)y,   nf * 32);
    zero_f4_kernel<<<cdiv(nf * 32, T), T>>>((float4*)acc, nf * 32);
    zero_i_kernel<<<cdiv(np, T), T>>>(degp, np);
    zero_i_kernel<<<cdiv(nf, T), T>>>(degf, nf);
    zero_i_kernel<<<cdiv(nf, T), T>>>(mask, nf);

    // 2. degrees + dinv
    deg_kernel<<<cdiv(ep, T), T>>>(pei + ep, ep, degp);
    deg_kernel<<<cdiv(ef, T), T>>>(ei + ef,  ef, degf);
    dinv_kernel<<<cdiv(np, T), T>>>(degp, dinvp, np);
    dinv_kernel<<<cdiv(nf, T), T>>>(degf, dinvf, nf);

    // 3. conv0 on pooled graph
    gemm_kernel<0><<<cdiv(np, 64), 256>>>(px, W0, np, dinvp, nullptr, ypool, accpool);
    edge_kernel<false><<<cdiv(ep, 8), 256>>>(pei, pei + ep, ep, ypool, accpool, nullptr);
    finalize_kernel<<<cdiv(np * 32, T), T>>>(accpool, dinvp, b0, h, np);

    // 4. conv1 on full graph (input is scatter(h) -> GEMM only 12.5k rows, masked edges)
    gemm_kernel<1><<<cdiv(np, 64), 256>>>(h, W1, np, dinvf, up, y, acc);
    mask_kernel<<<cdiv(np, T), T>>>(up, np, mask);
    edge_kernel<true><<<cdiv(ef, 8), 256>>>(ei, ei + ef, ef, y, acc, mask);
    finalize_kernel<<<cdiv(nf * 32, T), T>>>(acc, dinvf, b1, xf1, nf);

    // 5. conv2 on full graph (dense)
    gemm_kernel<0><<<cdiv(nf, 64), 256>>>(xf1, W2, nf, dinvf, nullptr, y, acc);
    edge_kernel<false><<<cdiv(ef, 8), 256>>>(ei, ei + ef, ef, y, acc, nullptr);
    finalize_kernel<<<cdiv(nf * 32, T), T>>>(acc, dinvf, b2, out, nf);
}

// round 2
// speedup vs baseline: 1.3607x; 1.3607x over previous
#include <cuda_runtime.h>
#include <math.h>

#define NFULL 50000
#define NPOOL 12500
#define EFULL 600000
#define EPOOL 150000
#define DD    128

// ---------------- device scratch (no allocation allowed) ----------------
__device__ float d_ypool[NPOOL * DD];
__device__ float d_h[NPOOL * DD];
__device__ float d_y[NFULL * DD];
__device__ float d_xf1[NFULL * DD];
__device__ int   d_degp[NPOOL];
__device__ int   d_degf[NFULL];
__device__ float d_dinvp[NPOOL];
__device__ float d_dinvf[NFULL];
__device__ int   d_offf[NFULL + 1];
__device__ int   d_offp[NPOOL + 1];
__device__ int   d_curf[NFULL];
__device__ int   d_curp[NPOOL];
__device__ int   d_csrf[EFULL];
__device__ int   d_csrp[EPOOL];

// ---------------- utility kernels ----------------
__global__ void zero_f4_kernel(float4* p, int n4) {
    int i = blockIdx.x * blockDim.x + threadIdx.x;
    int stride = gridDim.x * blockDim.x;
    float4 z = make_float4(0.f, 0.f, 0.f, 0.f);
    for (; i < n4; i += stride) p[i] = z;
}

__global__ void zero_i_kernel(int* p, int n) {
    int i = blockIdx.x * blockDim.x + threadIdx.x;
    int stride = gridDim.x * blockDim.x;
    for (; i < n; i += stride) p[i] = 0;
}

__global__ void deg_kernel(const int* __restrict__ dst, int E, int* __restrict__ deg) {
    int i = blockIdx.x * blockDim.x + threadIdx.x;
    int stride = gridDim.x * blockDim.x;
    for (; i < E; i += stride) atomicAdd(&deg[dst[i]], 1);
}

__global__ void dinv_kernel(const int* __restrict__ deg, float* __restrict__ dinv, int n) {
    int i = blockIdx.x * blockDim.x + threadIdx.x;
    int stride = gridDim.x * blockDim.x;
    for (; i < n; i += stride) dinv[i] = rsqrtf((float)(deg[i] + 1));
}

// single-block exclusive scan: off[0..n-1] = exclusive prefix of deg, off[n] = total
__global__ __launch_bounds__(1024) void scan_kernel(
    const int* __restrict__ deg, int* __restrict__ off, int n)
{
    __shared__ int warp_sums[32];
    __shared__ int carry_s;
    int tid = threadIdx.x;
    int lane = tid & 31;
    int wid = tid >> 5;
    if (tid == 0) carry_s = 0;
    __syncthreads();
    for (int base = 0; base < n; base += 1024) {
        int i = base + tid;
        int v = (i < n) ? deg[i] : 0;
        // inclusive warp scan
        int x = v;
#pragma unroll
        for (int d = 1; d < 32; d <<= 1) {
            int t = __shfl_up_sync(0xffffffffu, x, d);
            if (lane >= d) x += t;
        }
        if (lane == 31) warp_sums[wid] = x;
        __syncthreads();
        if (tid < 32) {
            int w = warp_sums[tid];
#pragma unroll
            for (int d = 1; d < 32; d <<= 1) {
                int t = __shfl_up_sync(0xffffffffu, w, d);
                if (tid >= d) w += t;
            }
            warp_sums[tid] = w;  // inclusive across warps
        }
        __syncthreads();
        int warp_excl = (wid > 0) ? warp_sums[wid - 1] : 0;
        int excl = (x - v) + warp_excl + carry_s;
        if (i < n) off[i] = excl;
        __syncthreads();
        if (tid == 1023) carry_s = excl + v;
        __syncthreads();
    }
    if (tid == 0) off[n] = carry_s;
}

__global__ void copy_i_kernel(const int* __restrict__ a, int* __restrict__ b, int n) {
    int i = blockIdx.x * blockDim.x + threadIdx.x;
    int stride = gridDim.x * blockDim.x;
    for (; i < n; i += stride) b[i] = a[i];
}

__global__ void csr_scatter_kernel(
    const int* __restrict__ src, const int* __restrict__ dst, int E,
    int* __restrict__ cursor, int* __restrict__ csr)
{
    int i = blockIdx.x * blockDim.x + threadIdx.x;
    int stride = gridDim.x * blockDim.x;
    for (; i < E; i += stride) {
        int d = dst[i];
        int pos = atomicAdd(&cursor[d], 1);
        csr[pos] = src[i];
    }
}

// ---------------- GEMM: y[node] = dinv[node] * (X[row] @ W) ----------------
// BM=64 rows x BN=128 cols (full D), BK=32. 256 threads, each 8x4 register tile.
template <int REMAP>
__global__ __launch_bounds__(256) void gemm_kernel(
    const float* __restrict__ X, const float* __restrict__ W, int M,
    const float* __restrict__ dinv, const int* __restrict__ remap,
    float* __restrict__ y)
{
    __shared__ float As[64][33];
    __shared__ float Bs[32][128];
    int tid = threadIdx.x;
    int tx = tid & 31;   // column group: cols tx*4 .. tx*4+3
    int ty = tid >> 5;   // row group: rows ty*8 .. ty*8+7
    int rowBase = blockIdx.x * 64;

    float accr[8][4];
#pragma unroll
    for (int r = 0; r < 8; r++)
#pragma unroll
        for (int c = 0; c < 4; c++) accr[r][c] = 0.f;

    for (int k0 = 0; k0 < 128; k0 += 32) {
#pragma unroll
        for (int s = 0; s < 2; s++) {
            int idx = tid * 2 + s;       // 0..511
            int r = idx >> 3;
            int c4 = idx & 7;
            float4 v = make_float4(0.f, 0.f, 0.f, 0.f);
            int grow = rowBase + r;
            if (grow < M) v = *(const float4*)(X + grow * 128 + k0 + c4 * 4);
            As[r][c4 * 4 + 0] = v.x;
            As[r][c4 * 4 + 1] = v.y;
            As[r][c4 * 4 + 2] = v.z;
            As[r][c4 * 4 + 3] = v.w;
        }
#pragma unroll
        for (int s = 0; s < 4; s++) {
            int idx = tid * 4 + s;       // 0..1023
            int r = idx >> 5;
            int c4 = idx & 31;
            float4 v = *(const float4*)(W + (k0 + r) * 128 + c4 * 4);
            *(float4*)&Bs[r][c4 * 4] = v;
        }
        __syncthreads();
#pragma unroll
        for (int k = 0; k < 32; k++) {
            float a[8];
#pragma unroll
            for (int r = 0; r < 8; r++) a[r] = As[ty * 8 + r][k];
            float4 b = *(float4*)&Bs[k][tx * 4];
#pragma unroll
            for (int r = 0; r < 8; r++) {
                accr[r][0] = fmaf(a[r], b.x, accr[r][0]);
                accr[r][1] = fmaf(a[r], b.y, accr[r][1]);
                accr[r][2] = fmaf(a[r], b.z, accr[r][2]);
                accr[r][3] = fmaf(a[r], b.w, accr[r][3]);
            }
        }
        __syncthreads();
    }

#pragma unroll
    for (int r = 0; r < 8; r++) {
        int row = rowBase + ty * 8 + r;
        if (row < M) {
            int node = REMAP ? remap[row] : row;
            float s = dinv[node];
            float4 v = make_float4(accr[r][0] * s, accr[r][1] * s,
                                   accr[r][2] * s, accr[r][3] * s);
            *(float4*)(y + node * 128 + tx * 4) = v;
        }
    }
}

// ---------------- fused gather + finalize ----------------
// out[d] = elu( dinv[d] * ( sum_{s in CSR[d]} y[s] + y[d] ) + b )
__device__ __forceinline__ float elu1(float x) {
    return x > 0.f ? x : expm1f(x);
}

__global__ __launch_bounds__(256) void gather_kernel(
    const int* __restrict__ off, const int* __restrict__ csr,
    const float* __restrict__ y, const float* __restrict__ dinv,
    const float* __restrict__ b, float* __restrict__ out, int n)
{
    int lane = threadIdx.x & 31;
    int node = (blockIdx.x * blockDim.x + threadIdx.x) >> 5;
    if (node >= n) return;
    int e0 = __ldg(&off[node]);
    int e1 = __ldg(&off[node + 1]);
    const float* yl = y + lane * 4;

    // self-loop term
    float4 a0 = *(const float4*)(yl + (size_t)node * 128);
    float4 a1 = make_float4(0.f, 0.f, 0.f, 0.f);

    int e = e0;
    for (; e + 2 <= e1; e += 2) {
        int sA = __ldg(&csr[e]);
        int sB = __ldg(&csr[e + 1]);
        float4 vA = *(const float4*)(yl + (size_t)sA * 128);
        float4 vB = *(const float4*)(yl + (size_t)sB * 128);
        a0.x += vA.x; a0.y += vA.y; a0.z += vA.z; a0.w += vA.w;
        a1.x += vB.x; a1.y += vB.y; a1.z += vB.z; a1.w += vB.w;
    }
    if (e < e1) {
        int sA = __ldg(&csr[e]);
        float4 vA = *(const float4*)(yl + (size_t)sA * 128);
        a0.x += vA.x; a0.y += vA.y; a0.z += vA.z; a0.w += vA.w;
    }
    a0.x += a1.x; a0.y += a1.y; a0.z += a1.z; a0.w += a1.w;

    float s = __ldg(&dinv[node]);
    float4 bb = *(const float4*)(b + lane * 4);
    float4 o;
    o.x = elu1(fmaf(s, a0.x, bb.x));
    o.y = elu1(fmaf(s, a0.y, bb.y));
    o.z = elu1(fmaf(s, a0.z, bb.z));
    o.w = elu1(fmaf(s, a0.w, bb.w));
    *(float4*)(out + (size_t)node * 128 + lane * 4) = o;
}

// ---------------- launch ----------------
extern "C" void kernel_launch(void* const* d_in, const int* in_sizes, int n_in,
                              void* d_out, int out_size)
{
    const int* ei  = (const int*)d_in[1];
    const float* px = (const float*)d_in[2];
    const int* pei = (const int*)d_in[3];
    const int* up  = (const int*)d_in[4];
    const float* W0 = (const float*)d_in[5];
    const float* b0 = (const float*)d_in[6];
    const float* W1 = (const float*)d_in[7];
    const float* b1 = (const float*)d_in[8];
    const float* W2 = (const float*)d_in[9];
    const float* b2 = (const float*)d_in[10];
    float* out = (float*)d_out;

    int nf = in_sizes[0] / DD;
    int ef = in_sizes[1] / 2;
    int np = in_sizes[2] / DD;
    int ep = in_sizes[3] / 2;

    // resolve device scratch addresses
    float *ypool, *h, *y, *xf1, *dinvp, *dinvf;
    int *degp, *degf, *offf, *offp, *curf, *curp, *csrf, *csrp;
    cudaGetSymbolAddress((void**)&ypool,  d_ypool);
    cudaGetSymbolAddress((void**)&h,      d_h);
    cudaGetSymbolAddress((void**)&y,      d_y);
    cudaGetSymbolAddress((void**)&xf1,    d_xf1);
    cudaGetSymbolAddress((void**)&degp,   d_degp);
    cudaGetSymbolAddress((void**)&degf,   d_degf);
    cudaGetSymbolAddress((void**)&dinvp,  d_dinvp);
    cudaGetSymbolAddress((void**)&dinvf,  d_dinvf);
    cudaGetSymbolAddress((void**)&offf,   d_offf);
    cudaGetSymbolAddress((void**)&offp,   d_offp);
    cudaGetSymbolAddress((void**)&curf,   d_curf);
    cudaGetSymbolAddress((void**)&curp,   d_curp);
    cudaGetSymbolAddress((void**)&csrf,   d_csrf);
    cudaGetSymbolAddress((void**)&csrp,   d_csrp);

    const int T = 256;
    auto cdiv = [](int a, int b) { return (a + b - 1) / b; };

    // 1. zero y (needed so non-kept rows read as exact zero in conv1) + degree bufs
    zero_f4_kernel<<<592, T>>>((float4*)y, nf * 32);
    zero_i_kernel<<<cdiv(np, T), T>>>(degp, np);
    zero_i_kernel<<<cdiv(nf, T), T>>>(degf, nf);

    // 2. degrees + dinv
    deg_kernel<<<cdiv(ep, T) < 592 ? cdiv(ep, T) : 592, T>>>(pei + ep, ep, degp);
    deg_kernel<<<592, T>>>(ei + ef, ef, degf);
    dinv_kernel<<<cdiv(np, T), T>>>(degp, dinvp, np);
    dinv_kernel<<<cdiv(nf, T), T>>>(degf, dinvf, nf);

    // 3. CSR build (full graph once, reused by conv1 + conv2; pooled once)
    scan_kernel<<<1, 1024>>>(degf, offf, nf);
    scan_kernel<<<1, 1024>>>(degp, offp, np);
    copy_i_kernel<<<cdiv(nf, T), T>>>(offf, curf, nf);
    copy_i_kernel<<<cdiv(np, T), T>>>(offp, curp, np);
    csr_scatter_kernel<<<592, T>>>(ei, ei + ef, ef, curf, csrf);
    csr_scatter_kernel<<<cdiv(ep, T) < 592 ? cdiv(ep, T) : 592, T>>>(pei, pei + ep, ep, curp, csrp);

    // 4. conv0 on pooled graph
    gemm_kernel<0><<<cdiv(np, 64), 256>>>(px, W0, np, dinvp, nullptr, ypool);
    gather_kernel<<<cdiv(np, 8), 256>>>(offp, csrp, ypool, dinvp, b0, h, np);

    // 5. conv1 on full graph: input = scatter(h) -> GEMM only 12.5k rows into zeroed y
    gemm_kernel<1><<<cdiv(np, 64), 256>>>(h, W1, np, dinvf, up, y);
    gather_kernel<<<cdiv(nf, 8), 256>>>(offf, csrf, y, dinvf, b1, xf1, nf);

    // 6. conv2 on full graph (dense; gemm overwrites all of y)
    gemm_kernel<0><<<cdiv(nf, 64), 256>>>(xf1, W2, nf, dinvf, nullptr, y);
    gather_kernel<<<cdiv(nf, 8), 256>>>(offf, csrf, y, dinvf, b2, out, nf);
}

// round 11
// speedup vs baseline: 1.6372x; 1.2031x over previous
#include <cuda_runtime.h>
#include <math.h>

#define NFULL 50000
#define NPOOL 12500
#define EFULL 600000
#define EPOOL 150000
#define DD    128
#define NBF   ((NFULL + 1023) / 1024)   // 49
#define NBP   ((NPOOL + 1023) / 1024)   // 13

// ---------------- device scratch (no allocation allowed) ----------------
__device__ float d_ypool[NPOOL * DD];
__device__ float d_h[NPOOL * DD];
__device__ float d_y[NFULL * DD];
__device__ float d_xf1[NFULL * DD];
__device__ int   d_degp[NPOOL];
__device__ int   d_degf[NFULL];
__device__ int   d_offf[NFULL + 1];
__device__ int   d_offp[NPOOL + 1];
__device__ int   d_cntf[NFULL];
__device__ int   d_cntp[NPOOL];
__device__ int   d_csrf[EFULL];
__device__ int   d_csrp[EPOOL];
__device__ int   d_mask[NFULL];
__device__ int   d_sumsF[64];
__device__ int   d_sumsP[64];

// ---------------- packed f32x2 asm ----------------
#define FMA2(acc, a, b) \
    asm("fma.rn.f32x2 %0, %1, %2, %0;" : "+l"(acc) : "l"(a), "l"(b))
#define PACK2(out, lo, hi) \
    asm("mov.b64 %0, {%1, %2};" : "=l"(out) : "f"(lo), "f"(hi))
#define UNPACK2(lo, hi, in) \
    asm("mov.b64 {%0, %1}, %2;" : "=f"(lo), "=f"(hi) : "l"(in))

// ---------------- small kernels ----------------
// batched degree count: y=0 full graph, y=1 pooled graph
__global__ void deg_kernel(const int* __restrict__ dstF, int EF, int* __restrict__ degF,
                           const int* __restrict__ dstP, int EP, int* __restrict__ degP)
{
    const int* dst = blockIdx.y ? dstP : dstF;
    int E = blockIdx.y ? EP : EF;
    int* deg = blockIdx.y ? degP : degF;
    int i = blockIdx.x * blockDim.x + threadIdx.x;
    int stride = gridDim.x * blockDim.x;
    for (; i < E; i += stride) atomicAdd(&deg[dst[i]], 1);
}

__global__ void mask_kernel(const int* __restrict__ remap, int n, int* __restrict__ mask)
{
    int i = blockIdx.x * blockDim.x + threadIdx.x;
    if (i < n) mask[remap[i]] = 1;
}

// ---- 3-phase parallel exclusive scan (both graphs batched via blockIdx.y) ----
__global__ __launch_bounds__(1024) void scan_p1(
    const int* __restrict__ degF, int nF, int* __restrict__ sumsF,
    const int* __restrict__ degP, int nP, int* __restrict__ sumsP)
{
    const int* deg = blockIdx.y ? degP : degF;
    int n = blockIdx.y ? nP : nF;
    int* sums = blockIdx.y ? sumsP : sumsF;
    int base = blockIdx.x * 1024;
    if (base >= n) return;
    int i = base + threadIdx.x;
    int v = (i < n) ? deg[i] : 0;
    __shared__ int ws[32];
    int lane = threadIdx.x & 31, wid = threadIdx.x >> 5;
#pragma unroll
    for (int d = 16; d > 0; d >>= 1) v += __shfl_down_sync(0xffffffffu, v, d);
    if (lane == 0) ws[wid] = v;
    __syncthreads();
    if (wid == 0) {
        int t = ws[lane];
#pragma unroll
        for (int d = 16; d > 0; d >>= 1) t += __shfl_down_sync(0xffffffffu, t, d);
        if (lane == 0) sums[blockIdx.x] = t;
    }
}

__global__ void scan_p2(int* sumsF, int nbF, int* offFend, int EF,
                        int* sumsP, int nbP, int* offPend, int EP)
{
    __shared__ int sF[64], sP[64];
    int t = threadIdx.x;  // 64 threads
    if (t < nbF) sF[t] = sumsF[t];
    if (t < nbP) sP[t] = sumsP[t];
    __syncthreads();
    if (t == 0) {
        int run = 0;
        for (int b = 0; b < nbF; b++) { int v = sF[b]; sF[b] = run; run += v; }
        *offFend = EF;
    }
    if (t == 32) {
        int run = 0;
        for (int b = 0; b < nbP; b++) { int v = sP[b]; sP[b] = run; run += v; }
        *offPend = EP;
    }
    __syncthreads();
    if (t < nbF) sumsF[t] = sF[t];
    if (t < nbP) sumsP[t] = sP[t];
}

__global__ __launch_bounds__(1024) void scan_p3(
    const int* __restrict__ degF, int nF, const int* __restrict__ sumsF, int* __restrict__ offF,
    const int* __restrict__ degP, int nP, const int* __restrict__ sumsP, int* __restrict__ offP)
{
    const int* deg = blockIdx.y ? degP : degF;
    int n = blockIdx.y ? nP : nF;
    const int* sums = blockIdx.y ? sumsP : sumsF;
    int* off = blockIdx.y ? offP : offF;
    int base = blockIdx.x * 1024;
    if (base >= n) return;
    int i = base + threadIdx.x;
    int v = (i < n) ? deg[i] : 0;
    __shared__ int ws[32];
    int lane = threadIdx.x & 31, wid = threadIdx.x >> 5;
    int x = v;
#pragma unroll
    for (int d = 1; d < 32; d <<= 1) {
        int t = __shfl_up_sync(0xffffffffu, x, d);
        if (lane >= d) x += t;
    }
    if (lane == 31) ws[wid] = x;
    __syncthreads();
    if (wid == 0) {
        int w = ws[lane];
#pragma unroll
        for (int d = 1; d < 32; d <<= 1) {
            int t = __shfl_up_sync(0xffffffffu, w, d);
            if (lane >= d) w += t;
        }
        ws[lane] = w;
    }
    __syncthreads();
    int excl = (x - v) + (wid > 0 ? ws[wid - 1] : 0) + sums[blockIdx.x];
    if (i < n) off[i] = excl;
}

// batched CSR build; full-graph entries carry kept-flag in bit 31
__global__ void csr_kernel(
    const int* __restrict__ srcF, const int* __restrict__ dstF, int EF,
    const int* __restrict__ offF, int* __restrict__ cntF, int* __restrict__ csrF,
    const int* __restrict__ mask,
    const int* __restrict__ srcP, const int* __restrict__ dstP, int EP,
    const int* __restrict__ offP, int* __restrict__ cntP, int* __restrict__ csrP)
{
    int i = blockIdx.x * blockDim.x + threadIdx.x;
    int stride = gridDim.x * blockDim.x;
    if (blockIdx.y == 0) {
        for (; i < EF; i += stride) {
            int d = dstF[i];
            int s = srcF[i];
            int pos = offF[d] + atomicAdd(&cntF[d], 1);
            csrF[pos] = s | (mask[s] ? 0x80000000 : 0);
        }
    } else {
        for (; i < EP; i += stride) {
            int d = dstP[i];
            int pos = offP[d] + atomicAdd(&cntP[d], 1);
            csrP[pos] = srcP[i];
        }
    }
}

// ---------------- GEMM: y[node] = dinv[node] * (X[row] @ W), f32x2 packed ----------------
// BM=64, BN=128 (full D), BK=32, 256 threads. Each thread: 4 row-pairs x 4 cols (f32x2 acc).
template <int REMAP>
__global__ __launch_bounds__(256) void gemm_kernel(
    const float* __restrict__ X, const float* __restrict__ W, int M,
    const int* __restrict__ off, const int* __restrict__ remap,
    float* __restrict__ y)
{
    __shared__ __align__(16) float AsT[32][66];   // [k][row], row-pairs contiguous
    __shared__ __align__(16) float Bs[32][128];
    int tid = threadIdx.x;
    int lane = tid & 31;   // column group: cols lane*4 .. +3
    int ty = tid >> 5;     // row group: rows ty*8 .. +7
    int rowBase = blockIdx.x * 64;

    unsigned long long acc[4][4];
#pragma unroll
    for (int rp = 0; rp < 4; rp++)
#pragma unroll
        for (int c = 0; c < 4; c++) acc[rp][c] = 0ull;

    for (int k0 = 0; k0 < 128; k0 += 32) {
        // stage A transposed: [k][row]
#pragma unroll
        for (int s = 0; s < 2; s++) {
            int idx = tid * 2 + s;        // 0..511
            int r = idx >> 3;             // row 0..63
            int c4 = idx & 7;             // k group of 4
            float4 v = make_float4(0.f, 0.f, 0.f, 0.f);
            int grow = rowBase + r;
            if (grow < M) v = *(const float4*)(X + (size_t)grow * 128 + k0 + c4 * 4);
            AsT[c4 * 4 + 0][r] = v.x;
            AsT[c4 * 4 + 1][r] = v.y;
            AsT[c4 * 4 + 2][r] = v.z;
            AsT[c4 * 4 + 3][r] = v.w;
        }
#pragma unroll
        for (int s = 0; s < 4; s++) {
            int idx = tid * 4 + s;        // 0..1023
            int r = idx >> 5;
            int c4 = idx & 31;
            *(float4*)&Bs[r][c4 * 4] = *(const float4*)(W + (size_t)(k0 + r) * 128 + c4 * 4);
        }
        __syncthreads();
#pragma unroll
        for (int k = 0; k < 32; k++) {
            unsigned long long a0 = *(const unsigned long long*)&AsT[k][ty * 8 + 0];
            unsigned long long a1 = *(const unsigned long long*)&AsT[k][ty * 8 + 2];
            unsigned long long a2 = *(const unsigned long long*)&AsT[k][ty * 8 + 4];
            unsigned long long a3 = *(const unsigned long long*)&AsT[k][ty * 8 + 6];
            float4 b = *(float4*)&Bs[k][lane * 4];
            unsigned long long bx, by, bz, bw;
            PACK2(bx, b.x, b.x);
            PACK2(by, b.y, b.y);
            PACK2(bz, b.z, b.z);
            PACK2(bw, b.w, b.w);
            FMA2(acc[0][0], a0, bx); FMA2(acc[0][1], a0, by);
            FMA2(acc[0][2], a0, bz); FMA2(acc[0][3], a0, bw);
            FMA2(acc[1][0], a1, bx); FMA2(acc[1][1], a1, by);
            FMA2(acc[1][2], a1, bz); FMA2(acc[1][3], a1, bw);
            FMA2(acc[2][0], a2, bx); FMA2(acc[2][1], a2, by);
            FMA2(acc[2][2], a2, bz); FMA2(acc[2][3], a2, bw);
            FMA2(acc[3][0], a3, bx); FMA2(acc[3][1], a3, by);
            FMA2(acc[3][2], a3, bz); FMA2(acc[3][3], a3, bw);
        }
        __syncthreads();
    }

#pragma unroll
    for (int rp = 0; rp < 4; rp++) {
        float lo0, hi0, lo1, hi1, lo2, hi2, lo3, hi3;
        UNPACK2(lo0, hi0, acc[rp][0]);
        UNPACK2(lo1, hi1, acc[rp][1]);
        UNPACK2(lo2, hi2, acc[rp][2]);
        UNPACK2(lo3, hi3, acc[rp][3]);
        int r0 = rowBase + ty * 8 + rp * 2;
        if (r0 < M) {
            int node = REMAP ? remap[r0] : r0;
            float s = rsqrtf((float)(off[node + 1] - off[node] + 1));
            float4 v = make_float4(lo0 * s, lo1 * s, lo2 * s, lo3 * s);
            *(float4*)(y + (size_t)node * 128 + lane * 4) = v;
        }
        if (r0 + 1 < M) {
            int node = REMAP ? remap[r0 + 1] : (r0 + 1);
            float s = rsqrtf((float)(off[node + 1] - off[node] + 1));
            float4 v = make_float4(hi0 * s, hi1 * s, hi2 * s, hi3 * s);
            *(float4*)(y + (size_t)node * 128 + lane * 4) = v;
        }
    }
}

// ---------------- fused gather + finalize ----------------
// out[d] = elu( dinv[d] * ( sum_{s in CSR[d]} y[s] + y[d] ) + b ),  dinv = rsqrt(deg+1)
// MODE 0: plain indices (pool). MODE 1: strip bit31 (full, all edges).
// MODE 2: only kept sources (bit31 set), self gated by mask (conv1).
__device__ __forceinline__ float elu1(float x) {
    return x > 0.f ? x : expm1f(x);
}

template <int MODE>
__global__ __launch_bounds__(256) void gather_kernel(
    const int* __restrict__ off, const int* __restrict__ csr,
    const float* __restrict__ y, const float* __restrict__ b,
    float* __restrict__ out, int n, const int* __restrict__ mask)
{
    int lane = threadIdx.x & 31;
    int node = (blockIdx.x * blockDim.x + threadIdx.x) >> 5;
    if (node >= n) return;
    int e0 = __ldg(&off[node]);
    int e1 = __ldg(&off[node + 1]);
    const float* yl = y + lane * 4;

    float4 a0 = make_float4(0.f, 0.f, 0.f, 0.f);
    float4 a1 = make_float4(0.f, 0.f, 0.f, 0.f);
    float4 a2 = make_float4(0.f, 0.f, 0.f, 0.f);
    float4 a3 = make_float4(0.f, 0.f, 0.f, 0.f);

    // self-loop term
    bool selfOk = (MODE == 2) ? (__ldg(&mask[node]) != 0) : true;
    if (selfOk) a0 = *(const float4*)(yl + (size_t)node * 128);

    int e = e0;
    if (MODE == 2) {
        int t = 0;
        for (; e < e1; e++) {
            int s = __ldg(&csr[e]);
            if (s >= 0) continue;   // source not kept -> row is exactly zero
            int i = s & 0x7fffffff;
            float4 v = *(const float4*)(yl + (size_t)i * 128);
            if (t & 1) { a1.x += v.x; a1.y += v.y; a1.z += v.z; a1.w += v.w; }
            else       { a0.x += v.x; a0.y += v.y; a0.z += v.z; a0.w += v.w; }
            t++;
        }
    } else {
        for (; e + 4 <= e1; e += 4) {
            int s0 = __ldg(&csr[e]);
            int s1 = __ldg(&csr[e + 1]);
            int s2 = __ldg(&csr[e + 2]);
            int s3 = __ldg(&csr[e + 3]);
            if (MODE == 1) {
                s0 &= 0x7fffffff; s1 &= 0x7fffffff;
                s2 &= 0x7fffffff; s3 &= 0x7fffffff;
            }
            float4 v0 = *(const float4*)(yl + (size_t)s0 * 128);
            float4 v1 = *(const float4*)(yl + (size_t)s1 * 128);
            float4 v2 = *(const float4*)(yl + (size_t)s2 * 128);
            float4 v3 = *(const float4*)(yl + (size_t)s3 * 128);
            a0.x += v0.x; a0.y += v0.y; a0.z += v0.z; a0.w += v0.w;
            a1.x += v1.x; a1.y += v1.y; a1.z += v1.z; a1.w += v1.w;
            a2.x += v2.x; a2.y += v2.y; a2.z += v2.z; a2.w += v2.w;
            a3.x += v3.x; a3.y += v3.y; a3.z += v3.z; a3.w += v3.w;
        }
        for (; e < e1; e++) {
            int s = __ldg(&csr[e]);
            if (MODE == 1) s &= 0x7fffffff;
            float4 v = *(const float4*)(yl + (size_t)s * 128);
            a0.x += v.x; a0.y += v.y; a0.z += v.z; a0.w += v.w;
        }
    }
    a0.x += a1.x + a2.x + a3.x;
    a0.y += a1.y + a2.y + a3.y;
    a0.z += a1.z + a2.z + a3.z;
    a0.w += a1.w + a2.w + a3.w;

    float s = rsqrtf((float)(e1 - e0 + 1));
    float4 bb = *(const float4*)(b + lane * 4);
    float4 o;
    o.x = elu1(fmaf(s, a0.x, bb.x));
    o.y = elu1(fmaf(s, a0.y, bb.y));
    o.z = elu1(fmaf(s, a0.z, bb.z));
    o.w = elu1(fmaf(s, a0.w, bb.w));
    *(float4*)(out + (size_t)node * 128 + lane * 4) = o;
}

// ---------------- launch ----------------
extern "C" void kernel_launch(void* const* d_in, const int* in_sizes, int n_in,
                              void* d_out, int out_size)
{
    const int* ei   = (const int*)d_in[1];
    const float* px = (const float*)d_in[2];
    const int* pei  = (const int*)d_in[3];
    const int* up   = (const int*)d_in[4];
    const float* W0 = (const float*)d_in[5];
    const float* b0 = (const float*)d_in[6];
    const float* W1 = (const float*)d_in[7];
    const float* b1 = (const float*)d_in[8];
    const float* W2 = (const float*)d_in[9];
    const float* b2 = (const float*)d_in[10];
    float* out = (float*)d_out;

    int nf = in_sizes[0] / DD;
    int ef = in_sizes[1] / 2;
    int np = in_sizes[2] / DD;
    int ep = in_sizes[3] / 2;

    float *ypool, *h, *y, *xf1;
    int *degp, *degf, *offf, *offp, *cntf, *cntp, *csrf, *csrp, *mask, *sumsF, *sumsP;
    cudaGetSymbolAddress((void**)&ypool, d_ypool);
    cudaGetSymbolAddress((void**)&h,     d_h);
    cudaGetSymbolAddress((void**)&y,     d_y);
    cudaGetSymbolAddress((void**)&xf1,   d_xf1);
    cudaGetSymbolAddress((void**)&degp,  d_degp);
    cudaGetSymbolAddress((void**)&degf,  d_degf);
    cudaGetSymbolAddress((void**)&offf,  d_offf);
    cudaGetSymbolAddress((void**)&offp,  d_offp);
    cudaGetSymbolAddress((void**)&cntf,  d_cntf);
    cudaGetSymbolAddress((void**)&cntp,  d_cntp);
    cudaGetSymbolAddress((void**)&csrf,  d_csrf);
    cudaGetSymbolAddress((void**)&csrp,  d_csrp);
    cudaGetSymbolAddress((void**)&mask,  d_mask);
    cudaGetSymbolAddress((void**)&sumsF, d_sumsF);
    cudaGetSymbolAddress((void**)&sumsP, d_sumsP);

    const int T = 256;
    auto cdiv = [](int a, int b) { return (a + b - 1) / b; };

    // zeroing via memset nodes
    cudaMemsetAsync(y,    0, (size_t)nf * DD * sizeof(float), 0);
    cudaMemsetAsync(degf, 0, nf * sizeof(int), 0);
    cudaMemsetAsync(degp, 0, np * sizeof(int), 0);
    cudaMemsetAsync(cntf, 0, nf * sizeof(int), 0);
    cudaMemsetAsync(cntp, 0, np * sizeof(int), 0);
    cudaMemsetAsync(mask, 0, nf * sizeof(int), 0);

    // degrees (both graphs), mask
    deg_kernel<<<dim3(586, 2), T>>>(ei + ef, ef, degf, pei + ep, ep, degp);
    mask_kernel<<<cdiv(np, T), T>>>(up, np, mask);

    // parallel exclusive scans (both graphs)
    scan_p1<<<dim3(NBF, 2), 1024>>>(degf, nf, sumsF, degp, np, sumsP);
    scan_p2<<<1, 64>>>(sumsF, NBF, offf + nf, ef, sumsP, NBP, offp + np, ep);
    scan_p3<<<dim3(NBF, 2), 1024>>>(degf, nf, sumsF, offf, degp, np, sumsP, offp);

    // CSR build (full graph flagged by kept-mask, pooled plain)
    csr_kernel<<<dim3(586, 2), T>>>(ei, ei + ef, ef, offf, cntf, csrf, mask,
                                    pei, pei + ep, ep, offp, cntp, csrp);

    // conv0 (pooled graph)
    gemm_kernel<0><<<cdiv(np, 64), 256>>>(px, W0, np, offp, nullptr, ypool);
    gather_kernel<0><<<cdiv(np * 32, T), T>>>(offp, csrp, ypool, b0, h, np, nullptr);

    // conv1 (full graph; GEMM only over 12.5k kept rows into zeroed y; gather skips unkept)
    gemm_kernel<1><<<cdiv(np, 64), 256>>>(h, W1, np, offf, up, y);
    gather_kernel<2><<<cdiv(nf * 32, T), T>>>(offf, csrf, y, b1, xf1, nf, mask);

    // conv2 (full graph, dense)
    gemm_kernel<0><<<cdiv(nf, 64), 256>>>(xf1, W2, nf, offf, nullptr, y);
    gather_kernel<1><<<cdiv(nf * 32, T), T>>>(offf, csrf, y, b2, out, nf, nullptr);
}

// round 14
// speedup vs baseline: 1.8166x; 1.1096x over previous
#include <cuda_runtime.h>
#include <math.h>

#define NFULL 50000
#define NPOOL 12500
#define EFULL 600000
#define EPOOL 150000
#define DD    128
#define NBF   ((NFULL + 1023) / 1024)   // 49
#define NBP   ((NPOOL + 1023) / 1024)   // 13

// ---------------- device scratch (no allocation allowed) ----------------
__device__ float d_ypool[NPOOL * DD];
__device__ float d_h[NPOOL * DD];
__device__ float d_y[NFULL * DD];
__device__ float d_xf1[NFULL * DD];
__device__ int   d_degp[NPOOL];
__device__ int   d_degf[NFULL];
__device__ int   d_offf[NFULL + 1];
__device__ int   d_offp[NPOOL + 1];
__device__ int   d_curfA[NFULL];   // front cursor (kept edges)
__device__ int   d_curfB[NFULL];   // back cursor (unkept edges)
__device__ int   d_curp[NPOOL];
__device__ int   d_curpB[NPOOL];
__device__ int   d_csrf[EFULL];
__device__ int   d_csrp[EPOOL];
__device__ int   d_mask[NFULL];
__device__ int   d_sumsF[64];
__device__ int   d_sumsP[64];

// ---------------- packed f32x2 asm ----------------
#define FMA2(acc, a, b) \
    asm("fma.rn.f32x2 %0, %1, %2, %0;" : "+l"(acc) : "l"(a), "l"(b))
#define PACK2(out, lo, hi) \
    asm("mov.b64 %0, {%1, %2};" : "=l"(out) : "f"(lo), "f"(hi))
#define UNPACK2(lo, hi, in) \
    asm("mov.b64 {%0, %1}, %2;" : "=f"(lo), "=f"(hi) : "l"(in))

// ---------------- fused degree + mask kernel ----------------
// blockIdx.y: 0 = full-graph degree, 1 = pooled degree, 2 = mask set
__global__ void degmask_kernel(
    const int* __restrict__ dstF, int EF, int* __restrict__ degF,
    const int* __restrict__ dstP, int EP, int* __restrict__ degP,
    const int* __restrict__ remap, int nP, int* __restrict__ mask)
{
    int i = blockIdx.x * blockDim.x + threadIdx.x;
    int stride = gridDim.x * blockDim.x;
    if (blockIdx.y == 0) {
        for (; i < EF; i += stride) atomicAdd(&degF[dstF[i]], 1);
    } else if (blockIdx.y == 1) {
        for (; i < EP; i += stride) atomicAdd(&degP[dstP[i]], 1);
    } else {
        for (; i < nP; i += stride) mask[remap[i]] = 1;
    }
}

// ---- 2-kernel parallel exclusive scan (both graphs batched via blockIdx.y) ----
__global__ __launch_bounds__(1024) void scan_p1(
    const int* __restrict__ degF, int nF, int* __restrict__ sumsF,
    const int* __restrict__ degP, int nP, int* __restrict__ sumsP)
{
    const int* deg = blockIdx.y ? degP : degF;
    int n = blockIdx.y ? nP : nF;
    int* sums = blockIdx.y ? sumsP : sumsF;
    int base = blockIdx.x * 1024;
    if (base >= n) return;
    int i = base + threadIdx.x;
    int v = (i < n) ? deg[i] : 0;
    __shared__ int ws[32];
    int lane = threadIdx.x & 31, wid = threadIdx.x >> 5;
#pragma unroll
    for (int d = 16; d > 0; d >>= 1) v += __shfl_down_sync(0xffffffffu, v, d);
    if (lane == 0) ws[wid] = v;
    __syncthreads();
    if (wid == 0) {
        int t = ws[lane];
#pragma unroll
        for (int d = 16; d > 0; d >>= 1) t += __shfl_down_sync(0xffffffffu, t, d);
        if (lane == 0) sums[blockIdx.x] = t;
    }
}

// phase 2+3 fused: each block reduces preceding block-sums itself, then scans
// its 1024 elements; writes off[i], both CSR cursors, and off[n] at the tail.
__global__ __launch_bounds__(1024) void scan_p3(
    const int* __restrict__ degF, int nF, const int* __restrict__ sumsF,
    int* __restrict__ offF, int* __restrict__ curAF, int* __restrict__ curBF,
    const int* __restrict__ degP, int nP, const int* __restrict__ sumsP,
    int* __restrict__ offP, int* __restrict__ curAP, int* __restrict__ curBP)
{
    const int* deg  = blockIdx.y ? degP  : degF;
    int n           = blockIdx.y ? nP    : nF;
    const int* sums = blockIdx.y ? sumsP : sumsF;
    int* off        = blockIdx.y ? offP  : offF;
    int* curA       = blockIdx.y ? curAP : curAF;
    int* curB       = blockIdx.y ? curBP : curBF;
    int base = blockIdx.x * 1024;
    if (base >= n) return;

    __shared__ int ws[32];
    __shared__ int red2[2];
    __shared__ int sumbase_s;
    int tid = threadIdx.x;
    int lane = tid & 31, wid = tid >> 5;

    // reduce sums[0 .. blockIdx.x) with first 64 threads (nb <= 49)
    if (tid < 64) {
        int v = (tid < blockIdx.x) ? sums[tid] : 0;
#pragma unroll
        for (int d = 16; d > 0; d >>= 1) v += __shfl_down_sync(0xffffffffu, v, d);
        if (lane == 0) red2[wid] = v;
    }
    __syncthreads();
    if (tid == 0) sumbase_s = red2[0] + red2[1];
    __syncthreads();

    int i = base + tid;
    int v = (i < n) ? deg[i] : 0;
    int x = v;
#pragma unroll
    for (int d = 1; d < 32; d <<= 1) {
        int t = __shfl_up_sync(0xffffffffu, x, d);
        if (lane >= d) x += t;
    }
    if (lane == 31) ws[wid] = x;
    __syncthreads();
    if (wid == 0) {
        int w = ws[lane];
#pragma unroll
        for (int d = 1; d < 32; d <<= 1) {
            int t = __shfl_up_sync(0xffffffffu, w, d);
            if (lane >= d) w += t;
        }
        ws[lane] = w;
    }
    __syncthreads();
    int excl = (x - v) + (wid > 0 ? ws[wid - 1] : 0) + sumbase_s;
    if (i < n) {
        off[i]  = excl;
        curA[i] = excl;        // front cursor (kept / all)
        curB[i] = excl + v;    // back cursor (unkept, decrements)
        if (i == n - 1) off[n] = excl + v;
    }
}

// batched CSR build. Full graph: kept-source edges compacted to the FRONT of
// each node's segment (bit31 flag set); unkept fill from the back.
__global__ void csr_kernel(
    const int* __restrict__ srcF, const int* __restrict__ dstF, int EF,
    int* __restrict__ curAF, int* __restrict__ curBF, int* __restrict__ csrF,
    const int* __restrict__ mask,
    const int* __restrict__ srcP, const int* __restrict__ dstP, int EP,
    int* __restrict__ curAP, int* __restrict__ csrP)
{
    int i = blockIdx.x * blockDim.x + threadIdx.x;
    int stride = gridDim.x * blockDim.x;
    if (blockIdx.y == 0) {
        for (; i < EF; i += stride) {
            int d = dstF[i];
            int s = srcF[i];
            if (mask[s]) {
                int pos = atomicAdd(&curAF[d], 1);
                csrF[pos] = s | 0x80000000;
            } else {
                int pos = atomicSub(&curBF[d], 1) - 1;
                csrF[pos] = s;
            }
        }
    } else {
        for (; i < EP; i += stride) {
            int d = dstP[i];
            int pos = atomicAdd(&curAP[d], 1);
            csrP[pos] = srcP[i];
        }
    }
}

// ---------------- GEMM: y[node] = dinv[node] * (X[row] @ W), f32x2 packed ----------------
// BM=64, BN=128 (full D), BK=32, 256 threads. Each thread: 4 row-pairs x 4 cols (f32x2 acc).
template <int REMAP>
__global__ __launch_bounds__(256) void gemm_kernel(
    const float* __restrict__ X, const float* __restrict__ W, int M,
    const int* __restrict__ off, const int* __restrict__ remap,
    float* __restrict__ y)
{
    __shared__ __align__(16) float AsT[32][66];   // [k][row], row-pairs contiguous
    __shared__ __align__(16) float Bs[32][128];
    int tid = threadIdx.x;
    int lane = tid & 31;   // column group: cols lane*4 .. +3
    int ty = tid >> 5;     // row group: rows ty*8 .. +7
    int rowBase = blockIdx.x * 64;

    unsigned long long acc[4][4];
#pragma unroll
    for (int rp = 0; rp < 4; rp++)
#pragma unroll
        for (int c = 0; c < 4; c++) acc[rp][c] = 0ull;

    for (int k0 = 0; k0 < 128; k0 += 32) {
        // stage A transposed: [k][row]
#pragma unroll
        for (int s = 0; s < 2; s++) {
            int idx = tid * 2 + s;        // 0..511
            int r = idx >> 3;             // row 0..63
            int c4 = idx & 7;             // k group of 4
            float4 v = make_float4(0.f, 0.f, 0.f, 0.f);
            int grow = rowBase + r;
            if (grow < M) v = *(const float4*)(X + (size_t)grow * 128 + k0 + c4 * 4);
            AsT[c4 * 4 + 0][r] = v.x;
            AsT[c4 * 4 + 1][r] = v.y;
            AsT[c4 * 4 + 2][r] = v.z;
            AsT[c4 * 4 + 3][r] = v.w;
        }
#pragma unroll
        for (int s = 0; s < 4; s++) {
            int idx = tid * 4 + s;        // 0..1023
            int r = idx >> 5;
            int c4 = idx & 31;
            *(float4*)&Bs[r][c4 * 4] = *(const float4*)(W + (size_t)(k0 + r) * 128 + c4 * 4);
        }
        __syncthreads();
#pragma unroll
        for (int k = 0; k < 32; k++) {
            unsigned long long a0 = *(const unsigned long long*)&AsT[k][ty * 8 + 0];
            unsigned long long a1 = *(const unsigned long long*)&AsT[k][ty * 8 + 2];
            unsigned long long a2 = *(const unsigned long long*)&AsT[k][ty * 8 + 4];
            unsigned long long a3 = *(const unsigned long long*)&AsT[k][ty * 8 + 6];
            float4 b = *(float4*)&Bs[k][lane * 4];
            unsigned long long bx, by, bz, bw;
            PACK2(bx, b.x, b.x);
            PACK2(by, b.y, b.y);
            PACK2(bz, b.z, b.z);
            PACK2(bw, b.w, b.w);
            FMA2(acc[0][0], a0, bx); FMA2(acc[0][1], a0, by);
            FMA2(acc[0][2], a0, bz); FMA2(acc[0][3], a0, bw);
            FMA2(acc[1][0], a1, bx); FMA2(acc[1][1], a1, by);
            FMA2(acc[1][2], a1, bz); FMA2(acc[1][3], a1, bw);
            FMA2(acc[2][0], a2, bx); FMA2(acc[2][1], a2, by);
            FMA2(acc[2][2], a2, bz); FMA2(acc[2][3], a2, bw);
            FMA2(acc[3][0], a3, bx); FMA2(acc[3][1], a3, by);
            FMA2(acc[3][2], a3, bz); FMA2(acc[3][3], a3, bw);
        }
        __syncthreads();
    }

#pragma unroll
    for (int rp = 0; rp < 4; rp++) {
        float lo0, hi0, lo1, hi1, lo2, hi2, lo3, hi3;
        UNPACK2(lo0, hi0, acc[rp][0]);
        UNPACK2(lo1, hi1, acc[rp][1]);
        UNPACK2(lo2, hi2, acc[rp][2]);
        UNPACK2(lo3, hi3, acc[rp][3]);
        int r0 = rowBase + ty * 8 + rp * 2;
        if (r0 < M) {
            int node = REMAP ? remap[r0] : r0;
            float s = rsqrtf((float)(off[node + 1] - off[node] + 1));
            float4 v = make_float4(lo0 * s, lo1 * s, lo2 * s, lo3 * s);
            *(float4*)(y + (size_t)node * 128 + lane * 4) = v;
        }
        if (r0 + 1 < M) {
            int node = REMAP ? remap[r0 + 1] : (r0 + 1);
            float s = rsqrtf((float)(off[node + 1] - off[node] + 1));
            float4 v = make_float4(hi0 * s, hi1 * s, hi2 * s, hi3 * s);
            *(float4*)(y + (size_t)node * 128 + lane * 4) = v;
        }
    }
}

// ---------------- fused gather + finalize ----------------
// out[d] = elu( dinv[d] * ( sum_{s in CSR[d]} y[s] + y[d] ) + b ),  dinv = rsqrt(deg+1)
// MODE 0: plain indices (pool). MODE 1: strip bit31 (full, all edges).
// MODE 2: kept edges are a compacted flagged prefix -> break at first unflagged;
//         self term gated by mask (conv1).
__device__ __forceinline__ float elu1(float x) {
    return x > 0.f ? x : expm1f(x);
}

template <int MODE>
__global__ __launch_bounds__(256) void gather_kernel(
    const int* __restrict__ off, const int* __restrict__ csr,
    const float* __restrict__ y, const float* __restrict__ b,
    float* __restrict__ out, int n, const int* __restrict__ mask)
{
    int lane = threadIdx.x & 31;
    int node = (blockIdx.x * blockDim.x + threadIdx.x) >> 5;
    if (node >= n) return;
    int e0 = __ldg(&off[node]);
    int e1 = __ldg(&off[node + 1]);
    const float* yl = y + lane * 4;

    float4 a0 = make_float4(0.f, 0.f, 0.f, 0.f);
    float4 a1 = make_float4(0.f, 0.f, 0.f, 0.f);
    float4 a2 = make_float4(0.f, 0.f, 0.f, 0.f);
    float4 a3 = make_float4(0.f, 0.f, 0.f, 0.f);

    // self-loop term
    bool selfOk = (MODE == 2) ? (__ldg(&mask[node]) != 0) : true;
    if (selfOk) a0 = *(const float4*)(yl + (size_t)node * 128);

    int e = e0;
    if (MODE == 2) {
        // kept edges are a flagged prefix: stop at first non-flagged entry
        for (; e + 2 <= e1; e += 2) {
            int sA = __ldg(&csr[e]);
            int sB = __ldg(&csr[e + 1]);
            if (sA >= 0) goto done;
            float4 vA = *(const float4*)(yl + (size_t)(sA & 0x7fffffff) * 128);
            a0.x += vA.x; a0.y += vA.y; a0.z += vA.z; a0.w += vA.w;
            if (sB >= 0) goto done;
            float4 vB = *(const float4*)(yl + (size_t)(sB & 0x7fffffff) * 128);
            a1.x += vB.x; a1.y += vB.y; a1.z += vB.z; a1.w += vB.w;
        }
        if (e < e1) {
            int sA = __ldg(&csr[e]);
            if (sA < 0) {
                float4 vA = *(const float4*)(yl + (size_t)(sA & 0x7fffffff) * 128);
                a0.x += vA.x; a0.y += vA.y; a0.z += vA.z; a0.w += vA.w;
            }
        }
        done: ;
    } else {
        for (; e + 4 <= e1; e += 4) {
            int s0 = __ldg(&csr[e]);
            int s1 = __ldg(&csr[e + 1]);
            int s2 = __ldg(&csr[e + 2]);
            int s3 = __ldg(&csr[e + 3]);
            if (MODE == 1) {
                s0 &= 0x7fffffff; s1 &= 0x7fffffff;
                s2 &= 0x7fffffff; s3 &= 0x7fffffff;
            }
            float4 v0 = *(const float4*)(yl + (size_t)s0 * 128);
            float4 v1 = *(const float4*)(yl + (size_t)s1 * 128);
            float4 v2 = *(const float4*)(yl + (size_t)s2 * 128);
            float4 v3 = *(const float4*)(yl + (size_t)s3 * 128);
            a0.x += v0.x; a0.y += v0.y; a0.z += v0.z; a0.w += v0.w;
            a1.x += v1.x; a1.y += v1.y; a1.z += v1.z; a1.w += v1.w;
            a2.x += v2.x; a2.y += v2.y; a2.z += v2.z; a2.w += v2.w;
            a3.x += v3.x; a3.y += v3.y; a3.z += v3.z; a3.w += v3.w;
        }
        for (; e < e1; e++) {
            int s = __ldg(&csr[e]);
            if (MODE == 1) s &= 0x7fffffff;
            float4 v = *(const float4*)(yl + (size_t)s * 128);
            a0.x += v.x; a0.y += v.y; a0.z += v.z; a0.w += v.w;
        }
    }
    a0.x += a1.x + a2.x + a3.x;
    a0.y += a1.y + a2.y + a3.y;
    a0.z += a1.z + a2.z + a3.z;
    a0.w += a1.w + a2.w + a3.w;

    float s = rsqrtf((float)(e1 - e0 + 1));
    float4 bb = *(const float4*)(b + lane * 4);
    float4 o;
    o.x = elu1(fmaf(s, a0.x, bb.x));
    o.y = elu1(fmaf(s, a0.y, bb.y));
    o.z = elu1(fmaf(s, a0.z, bb.z));
    o.w = elu1(fmaf(s, a0.w, bb.w));
    *(float4*)(out + (size_t)node * 128 + lane * 4) = o;
}

// ---------------- launch ----------------
extern "C" void kernel_launch(void* const* d_in, const int* in_sizes, int n_in,
                              void* d_out, int out_size)
{
    const int* ei   = (const int*)d_in[1];
    const float* px = (const float*)d_in[2];
    const int* pei  = (const int*)d_in[3];
    const int* up   = (const int*)d_in[4];
    const float* W0 = (const float*)d_in[5];
    const float* b0 = (const float*)d_in[6];
    const float* W1 = (const float*)d_in[7];
    const float* b1 = (const float*)d_in[8];
    const float* W2 = (const float*)d_in[9];
    const float* b2 = (const float*)d_in[10];
    float* out = (float*)d_out;

    int nf = in_sizes[0] / DD;
    int ef = in_sizes[1] / 2;
    int np = in_sizes[2] / DD;
    int ep = in_sizes[3] / 2;

    float *ypool, *h, *y, *xf1;
    int *degp, *degf, *offf, *offp, *curfA, *curfB, *curp, *curpB;
    int *csrf, *csrp, *mask, *sumsF, *sumsP;
    cudaGetSymbolAddress((void**)&ypool, d_ypool);
    cudaGetSymbolAddress((void**)&h,     d_h);
    cudaGetSymbolAddress((void**)&y,     d_y);
    cudaGetSymbolAddress((void**)&xf1,   d_xf1);
    cudaGetSymbolAddress((void**)&degp,  d_degp);
    cudaGetSymbolAddress((void**)&degf,  d_degf);
    cudaGetSymbolAddress((void**)&offf,  d_offf);
    cudaGetSymbolAddress((void**)&offp,  d_offp);
    cudaGetSymbolAddress((void**)&curfA, d_curfA);
    cudaGetSymbolAddress((void**)&curfB, d_curfB);
    cudaGetSymbolAddress((void**)&curp,  d_curp);
    cudaGetSymbolAddress((void**)&curpB, d_curpB);
    cudaGetSymbolAddress((void**)&csrf,  d_csrf);
    cudaGetSymbolAddress((void**)&csrp,  d_csrp);
    cudaGetSymbolAddress((void**)&mask,  d_mask);
    cudaGetSymbolAddress((void**)&sumsF, d_sumsF);
    cudaGetSymbolAddress((void**)&sumsP, d_sumsP);

    const int T = 256;
    auto cdiv = [](int a, int b) { return (a + b - 1) / b; };

    // only the atomic-counter arrays need zeroing each replay.
    // (mask is idempotent: same bits set every run; y memset removed — unkept
    //  rows are never read by the MODE-2 gather.)
    cudaMemsetAsync(degf, 0, nf * sizeof(int), 0);
    cudaMemsetAsync(degp, 0, np * sizeof(int), 0);

    // degrees (both graphs) + mask in one launch
    degmask_kernel<<<dim3(586, 3), T>>>(ei + ef, ef, degf, pei + ep, ep, degp,
                                        up, np, mask);

    // 2-kernel parallel exclusive scans; p3 also emits both CSR cursors
    scan_p1<<<dim3(NBF, 2), 1024>>>(degf, nf, sumsF, degp, np, sumsP);
    scan_p3<<<dim3(NBF, 2), 1024>>>(degf, nf, sumsF, offf, curfA, curfB,
                                    degp, np, sumsP, offp, curp, curpB);

    // CSR build (full graph: kept edges compacted to flagged prefix)
    csr_kernel<<<dim3(586, 2), T>>>(ei, ei + ef, ef, curfA, curfB, csrf, mask,
                                    pei, pei + ep, ep, curp, csrp);

    // conv0 (pooled graph)
    gemm_kernel<0><<<cdiv(np, 64), 256>>>(px, W0, np, offp, nullptr, ypool);
    gather_kernel<0><<<cdiv(np * 32, T), T>>>(offp, csrp, ypool, b0, h, np, nullptr);

    // conv1 (full graph; GEMM only over 12.5k kept rows; gather reads kept prefix only)
    gemm_kernel<1><<<cdiv(np, 64), 256>>>(h, W1, np, offf, up, y);
    gather_kernel<2><<<cdiv(nf * 32, T), T>>>(offf, csrf, y, b1, xf1, nf, mask);

    // conv2 (full graph, dense; gemm overwrites all of y)
    gemm_kernel<0><<<cdiv(nf, 64), 256>>>(xf1, W2, nf, offf, nullptr, y);
    gather_kernel<1><<<cdiv(nf * 32, T), T>>>(offf, csrf, y, b2, out, nf, nullptr);
}